// round 15
// baseline (speedup 1.0000x reference)
#include <cuda_runtime.h>
#include <math.h>

#define NT1 1024

typedef unsigned long long u64;

// Scratch (static device arrays — no allocation)
__device__ u64   g_state[32u * 65536u];   // 16 MB: [b][k][b0][b15][idx14], packed (re,im)
__device__ float g_featsP[4 * 16 * 24];   // partial quantum features [part][b][24]

// ---------------- f32x2 packed helpers (sm_103a) ----------------
__device__ __forceinline__ u64 pk2(float x, float y) {
    u64 r; asm("mov.b64 %0, {%1,%2};" : "=l"(r) : "f"(x), "f"(y)); return r;
}
__device__ __forceinline__ u64 f2mul(u64 a, u64 b) {
    u64 d; asm("mul.rn.f32x2 %0, %1, %2;" : "=l"(d) : "l"(a), "l"(b)); return d;
}
__device__ __forceinline__ u64 f2fma(u64 a, u64 b, u64 c) {
    u64 d; asm("fma.rn.f32x2 %0, %1, %2, %3;" : "=l"(d) : "l"(a), "l"(b), "l"(c)); return d;
}
__device__ __forceinline__ u64 f2swap(u64 a) {
    unsigned lo, hi; asm("mov.b64 {%0,%1}, %2;" : "=r"(lo), "=r"(hi) : "l"(a));
    u64 d; asm("mov.b64 %0, {%1,%2};" : "=l"(d) : "r"(hi), "r"(lo)); return d;
}
__device__ __forceinline__ void upk(u64 a, float& x, float& y) {
    asm("mov.b64 {%0,%1}, %2;" : "=f"(x), "=f"(y) : "l"(a));
}

// Bank-conflict-free swizzle; GF(2)-LINEAR: sphys(a^b) = sphys(a)^sphys(b)
// (5*y for 2-bit y = y|(y<<2), carry-free). Used to split base/lane parts.
__device__ __host__ __forceinline__ constexpr int sphys(int idx) {
    return idx ^ ((idx >> 2) & 12) ^ (5 * ((idx >> 6) & 3));
}

// RY on packed pair: u' = c*u - s*v ; v' = s*u + c*v (elementwise on re/im)
template<int T, int N>
__device__ __forceinline__ void ryg(u64* a, u64 cc, u64 ss, u64 nss) {
#pragma unroll
    for (int m = 0; m < N; m++) {
        if (m & (1 << T)) continue;
        int v = m | (1 << T);
        u64 au = a[m], av = a[v];
        a[m] = f2fma(cc, au, f2mul(nss, av));
        a[v] = f2fma(cc, av, f2mul(ss, au));
    }
}
// RX: u' = c*u + (s,-s)*swap(v) ; v' = c*v + (s,-s)*swap(u)
template<int T, int N>
__device__ __forceinline__ void rxg(u64* a, u64 cc, u64 sp) {
#pragma unroll
    for (int m = 0; m < N; m++) {
        if (m & (1 << T)) continue;
        int v = m | (1 << T);
        u64 au = a[m], av = a[v];
        a[m] = f2fma(cc, au, f2mul(sp, f2swap(av)));
        a[v] = f2fma(cc, av, f2mul(sp, f2swap(au)));
    }
}
template<int C, int T, int N>
__device__ __forceinline__ void cng(u64* a) {
#pragma unroll
    for (int m = 0; m < N; m++) {
        if (!(m & (1 << C)) || (m & (1 << T))) continue;
        int v = m | (1 << T);
        u64 t = a[m]; a[m] = a[v]; a[v] = t;
    }
}

// ---------------- compile-time parity masks for the 36-CNOT cascade ----------------
// inner: e5 bits (bit4=wire11 .. bit0=wire15); outer: idx14 bits 13..4 (wires 1..10)
struct Masks { unsigned inner[12]; unsigned outer14[12]; unsigned w0f[12]; };
__host__ __device__ constexpr Masks compute_masks() {
    Masks M{};
    int cs[36] = {}, ts2[36] = {}; int n = 0;
    for (int i = 0; i < 12; i++) {
        cs[n] = i + 1; ts2[n] = i; n++;
        cs[n] = i + 3; ts2[n] = i; n++;
        cs[n] = i + 4; ts2[n] = i; n++;
    }
    for (int w = 0; w < 12; w++) {
        unsigned m = 1u << w;
        for (int j = 35; j >= 0; --j)
            if ((m >> ts2[j]) & 1u) m ^= 1u << cs[j];
        unsigned inner = 0, outer = 0;
        M.w0f[w] = m & 1u;
        for (int ww = 1; ww <= 10; ++ww)
            if ((m >> ww) & 1u) outer |= 1u << (14 - ww);
        for (int ww = 11; ww <= 15; ++ww)
            if ((m >> ww) & 1u) inner |= 1u << (15 - ww);
        M.inner[w] = inner; M.outer14[w] = outer;
    }
    return M;
}

// ---------------- kernel 1: 14-qubit smem-resident simulation ----------------
// 128 blocks: bi = ((b*2 + k)*2 + b0)*2 + b15. Pooling folded into prologue.
// Offsets via linearity of sphys: off[e] = sphys(base) ^ const.
extern "C" __global__ void __launch_bounds__(NT1) qsim_k1(
    const float* __restrict__ x, const float* __restrict__ kp)
{
    extern __shared__ u64 S[];           // 16384 amps (swizzled)
    __shared__ float tws[16][2];
    __shared__ float ptrig[5][2];
    int tid = threadIdx.x;
    int bi = blockIdx.x;
    int b = bi >> 3, k = (bi >> 2) & 1, bb0 = (bi >> 1) & 1, bb15 = bi & 1;

    if (tid < 16) {
        // fused 7x7 avg pool for cell tid of batch b
        int r = tid >> 2, c = tid & 3;
        const float* px = x + b * 784 + r * 7 * 28 + c * 7;
        float s = 0.f;
#pragma unroll
        for (int u = 0; u < 7; u++)
#pragma unroll
            for (int v = 0; v < 7; v++) s += px[u * 28 + v];
        float ang = s * (1.f / 49.f);
        if (tid == 0) ang += kp[k * 5];      // fold iter-0 RY(p0) on wire 0
        float h = 0.5f * ang;
        tws[tid][0] = cosf(h); tws[tid][1] = sinf(h);
    }
    if (tid < 5) {
        float h = 0.5f * kp[k * 5 + tid];
        ptrig[tid][0] = cosf(h); ptrig[tid][1] = sinf(h);
    }
    __syncthreads();

    float c0 = ptrig[0][0], s0 = ptrig[0][1];
    float c1 = ptrig[1][0], s1 = ptrig[1][1];
    float c2 = ptrig[2][0], s2 = ptrig[2][1];
    float c3 = ptrig[3][0], s3 = ptrig[3][1];
    float c4 = ptrig[4][0], s4 = ptrig[4][1];
    u64 cc0 = pk2(c0, c0), ss0 = pk2(s0, s0), ns0 = pk2(-s0, -s0);
    u64 cc1 = pk2(c1, c1), ss1 = pk2(s1, s1), ns1 = pk2(-s1, -s1);
    u64 cc2 = pk2(c2, c2), ss2 = pk2(s2, s2), ns2 = pk2(-s2, -s2);
    u64 cc3 = pk2(c3, c3), sp3 = pk2(s3, -s3);
    u64 cc4 = pk2(c4, c4), sp4 = pk2(s4, -s4);

    int stid = sphys(tid);   // linear part for strided loops (stride bits ^ tid bits disjoint)

    // ---- init: product state, factored (encoder folded; CNOT(0,3) as table swap) ----
    {
        float A = tws[0][bb0] * tws[15][bb15];
        float tc[14], ts[14];
#pragma unroll
        for (int w = 1; w <= 14; ++w) { tc[w - 1] = tws[w][0]; ts[w - 1] = tws[w][1]; }
        if (bb0) { float t = tc[2]; tc[2] = ts[2]; ts[2] = t; }   // X on wire 3 when wire0==1
        // P over j bits 0..9 (tables 13..4), scaled by A
        float P = A;
#pragma unroll
        for (int j = 0; j < 10; j++)
            P *= ((tid >> j) & 1) ? ts[13 - j] : tc[13 - j];
        // two-level factor tables for j bits 10..13 (tables 3..0)
        float fa[4], fb[4];
#pragma unroll
        for (int q = 0; q < 4; q++) {
            fa[q] = ((q & 1) ? ts[3] : tc[3]) * ((q & 2) ? ts[2] : tc[2]);  // j bits 10,11
            fb[q] = ((q & 1) ? ts[1] : tc[1]) * ((q & 2) ? ts[0] : tc[0]);  // j bits 12,13
        }
#pragma unroll
        for (int m = 0; m < 16; m++) {
            float amp = P * fa[m & 3] * fb[m >> 2];
            S[stid ^ sphys(m << 10)] = pk2(amp, 0.f);
        }
    }
    __syncthreads();

    // ---- iteration 0 (wires 1,3,4 local; wire-0 ops folded) ----
    for (int g = tid; g < 2048; g += NT1) {
        // mask bits {13,11,10}; non-mask: bits 0..9 and bit 12
        int base = (g & 0x3FF) | ((g >> 10) << 12);
        int pb = sphys(base);
        int off[8]; u64 a[8];
#pragma unroll
        for (int e = 0; e < 8; e++) {
            off[e] = pb ^ sphys(((e & 3) << 10) | ((e >> 2) << 13));
            a[e] = S[off[e]];
        }
        ryg<1, 8>(a, cc1, ss1, ns1);  // RY(p1) wire 3
        ryg<2, 8>(a, cc2, ss2, ns2);  // RY(p2) wire 1
        cng<2, 0, 8>(a);              // CNOT(1,4)
        cng<1, 2, 8>(a);              // CNOT(3,1)
        rxg<0, 8>(a, cc3, sp3);       // RX(p3) wire 4
        rxg<2, 8>(a, cc4, sp4);       // RX(p4) wire 1
#pragma unroll
        for (int e = 0; e < 8; e++) S[off[e]] = a[e];
    }
    __syncthreads();

    // ---- iterations 1..10 (generic 4-bit group: wires i,i+1,i+3,i+4) ----
    // FULLY UNROLLED: masks/shifts and lane-swizzles are compile-time constants.
#pragma unroll
    for (int i = 1; i <= 10; i++) {
        const int B0 = 10 - i, B2 = 13 - i;
        {
            int g = tid;                 // 1024 groups, 1024 threads
            int low = g & ((1 << B0) - 1);
            int rest = g >> B0;
            int base = low | ((rest & 1) << (B0 + 2)) | ((rest >> 1) << (B0 + 5));
            int pb = sphys(base);
            int off[16]; u64 a[16];
#pragma unroll
            for (int e = 0; e < 16; e++) {
                off[e] = pb ^ sphys(((e & 3) << B0) | ((e >> 2) << B2));
                a[e] = S[off[e]];
            }
            ryg<3, 16>(a, cc0, ss0, ns0);   // RY(p0) wire i
            cng<3, 1, 16>(a);               // CNOT(i, i+3)
            ryg<1, 16>(a, cc1, ss1, ns1);   // RY(p1) wire i+3
            ryg<2, 16>(a, cc2, ss2, ns2);   // RY(p2) wire i+1
            cng<2, 0, 16>(a);               // CNOT(i+1, i+4)
            cng<1, 2, 16>(a);               // CNOT(i+3, i+1)
            rxg<0, 16>(a, cc3, sp3);        // RX(p3) wire i+4
            rxg<2, 16>(a, cc4, sp4);        // RX(p4) wire i+1
#pragma unroll
            for (int e = 0; e < 16; e++) S[off[e]] = a[e];
        }
        __syncthreads();
    }

    // ---- spill sub-state (coalesced); iteration 11 handled in k2 ----
    u64* outp = g_state + (size_t)bi * 16384u;
#pragma unroll
    for (int m = 0; m < 16; m++)
        outp[tid + (m << 10)] = S[stid ^ sphys(m << 10)];
}

// ---------------- kernel 2: iteration 11 + measurement (5-bit WHT) ----------------
// 128 blocks = 32 statevectors x 4 partial slices; 512 threads, 1 group/thread.
// Groups of 32 amps over wires 11..15 (e5: bit4=w11, bit3=w12, bit2=w13, bit1=w14, bit0=w15).
extern "C" __global__ void __launch_bounds__(512) qsim_k2(const float* __restrict__ kp) {
    constexpr Masks MK = compute_masks();
    int tid = threadIdx.x;
    int blk = blockIdx.x;
    int bk = blk >> 2, part = blk & 3;
    int b = bk >> 1, k = bk & 1;

    float c0, s0, c1, s1, c2, s2, c3, s3, c4, s4;
    { float h = 0.5f * kp[k * 5 + 0]; c0 = cosf(h); s0 = sinf(h); }
    { float h = 0.5f * kp[k * 5 + 1]; c1 = cosf(h); s1 = sinf(h); }
    { float h = 0.5f * kp[k * 5 + 2]; c2 = cosf(h); s2 = sinf(h); }
    { float h = 0.5f * kp[k * 5 + 3]; c3 = cosf(h); s3 = sinf(h); }
    { float h = 0.5f * kp[k * 5 + 4]; c4 = cosf(h); s4 = sinf(h); }
    u64 cc0 = pk2(c0, c0), ss0 = pk2(s0, s0), ns0 = pk2(-s0, -s0);
    u64 cc1 = pk2(c1, c1), ss1 = pk2(s1, s1), ns1 = pk2(-s1, -s1);
    u64 cc2 = pk2(c2, c2), ss2 = pk2(s2, s2), ns2 = pk2(-s2, -s2);
    u64 cc3 = pk2(c3, c3), sp3 = pk2(s3, -s3);
    u64 cc4 = pk2(c4, c4), sp4 = pk2(s4, -s4);

    const u64* base = g_state + (size_t)bk * 65536u;
    float acc[12];
#pragma unroll
    for (int w = 0; w < 12; w++) acc[w] = 0.f;

    // 2048 groups per statevector: gi = b0(bit10) | idx14_hi(10 bits); 1 per thread
    {
        int gi = part * 512 + tid;
        int b0 = gi >> 10, hi = gi & 1023;
        const u64* p = base + b0 * 32768 + hi * 16;
        u64 a[32];
#pragma unroll
        for (int o = 0; o < 16; o++) {       // o bits 3..0 = wires 11,12,13,14
            a[(o << 1)]     = p[o];          // b15 (wire15) = 0
            a[(o << 1) | 1] = p[o + 16384];  // wire15 = 1
        }
        // iteration 11 (full):
        ryg<4, 32>(a, cc0, ss0, ns0);   // RY(p0) wire 11
        cng<4, 1, 32>(a);               // CNOT(11,14)
        ryg<1, 32>(a, cc1, ss1, ns1);   // RY(p1) wire 14
        ryg<3, 32>(a, cc2, ss2, ns2);   // RY(p2) wire 12
        cng<3, 0, 32>(a);               // CNOT(12,15)
        cng<1, 3, 32>(a);               // CNOT(14,12)
        rxg<0, 32>(a, cc3, sp3);        // RX(p3) wire 15
        rxg<3, 32>(a, cc4, sp4);        // RX(p4) wire 12
        float pr[32];
#pragma unroll
        for (int e = 0; e < 32; e++) {
            float xr, xi; upk(a[e], xr, xi);
            pr[e] = xr * xr + xi * xi;
        }
        // 5-bit Walsh-Hadamard: pr[m] <- sum_e (-1)^{popc(m&e)} pr[e]
#pragma unroll
        for (int bit = 1; bit < 32; bit <<= 1) {
#pragma unroll
            for (int m = 0; m < 32; m++) {
                if (m & bit) continue;
                float u = pr[m], v = pr[m | bit];
                pr[m] = u + v; pr[m | bit] = u - v;
            }
        }
        int base14 = hi << 4;
#pragma unroll
        for (int w = 0; w < 12; w++) {
            float s = pr[MK.inner[w]];
            int par = (__popc(base14 & MK.outer14[w]) + (b0 & MK.w0f[w])) & 1;
            acc[w] += par ? -s : s;
        }
    }
    // deterministic reduction (16 warps)
#pragma unroll
    for (int w = 0; w < 12; w++)
        for (int o = 16; o > 0; o >>= 1)
            acc[w] += __shfl_xor_sync(0xffffffffu, acc[w], o);
    __shared__ float part_s[16][12];
    int wid = tid >> 5, lane = tid & 31;
    if (lane == 0) {
#pragma unroll
        for (int w = 0; w < 12; w++) part_s[wid][w] = acc[w];
    }
    __syncthreads();
    if (tid < 12) {
        float s = 0.f;
#pragma unroll
        for (int r = 0; r < 16; r++) s += part_s[r][tid];
        g_featsP[part * 384 + b * 24 + k * 12 + tid] = s;
    }
}

// ---------------- kernel 3: tiny MLP 24->128->64->4 ----------------
// 16 blocks (one per batch item), 256 threads. Weights staged via float4
// global loads; padded smem strides (25 / 129) keep LDS conflict-free.
#define K3_SMEM_FLOATS 12380
extern "C" __global__ void __launch_bounds__(256) qsim_k3(
    const float* __restrict__ w1, const float* __restrict__ bb1,
    const float* __restrict__ w2, const float* __restrict__ bb2,
    const float* __restrict__ w3, const float* __restrict__ bb3,
    float* __restrict__ out)
{
    extern __shared__ float sm[];
    float* w1s = sm;             // 128 x stride 25  (3200)
    float* w2s = sm + 3200;      // 64 x stride 129  (8256)
    float* w3s = sm + 11456;     // 256
    float* b1s = sm + 11712;     // 128
    float* b2s = sm + 11840;     // 64
    float* b3s = sm + 11904;     // 4
    float* fts = sm + 11908;     // 24
    float* h1  = sm + 11936;     // 128
    float* h2  = sm + 12064;     // 64
    float* prt = sm + 12124;     // 256

    int tid = threadIdx.x;
    int b = blockIdx.x;

    // ---- stage weights (float4 global reads, scalar padded STS) ----
    const float4* w1v = (const float4*)w1;
    for (int t = tid; t < 768; t += 256) {
        float4 v = w1v[t];
        int base = 4 * t, row = base / 24, col = base % 24;
        float* d = w1s + row * 25 + col;
        d[0] = v.x; d[1] = v.y; d[2] = v.z; d[3] = v.w;
    }
    const float4* w2v = (const float4*)w2;
    for (int t = tid; t < 2048; t += 256) {
        float4 v = w2v[t];
        int base = 4 * t, row = base >> 7, col = base & 127;
        float* d = w2s + row * 129 + col;
        d[0] = v.x; d[1] = v.y; d[2] = v.z; d[3] = v.w;
    }
    if (tid < 64) {
        float4 v = ((const float4*)w3)[tid];
        float* d = w3s + 4 * tid;
        d[0] = v.x; d[1] = v.y; d[2] = v.z; d[3] = v.w;
    }
    if (tid < 128) b1s[tid] = bb1[tid];
    if (tid < 64)  b2s[tid] = bb2[tid];
    if (tid < 4)   b3s[tid] = bb3[tid];
    if (tid < 24) {
        float s = g_featsP[b * 24 + tid] + g_featsP[384 + b * 24 + tid]
                + g_featsP[768 + b * 24 + tid] + g_featsP[1152 + b * 24 + tid];
        fts[tid] = s;
    }
    __syncthreads();

    // ---- fc1: one output unit per thread (threads 0..127) ----
    if (tid < 128) {
        float s = b1s[tid];
        const float* wr = w1s + tid * 25;
#pragma unroll
        for (int i = 0; i < 24; i++) s += wr[i] * fts[i];
        h1[tid] = fmaxf(s, 0.f);
    }
    __syncthreads();

    // ---- fc2: 64 units, 4 threads per unit (split the 128-dot into 32s) ----
    {
        int j = tid & 63, h = tid >> 6;
        const float* wr = w2s + j * 129 + h * 32;
        const float* hr = h1 + h * 32;
        float s = 0.f;
#pragma unroll
        for (int i = 0; i < 32; i++) s += wr[i] * hr[i];
        prt[tid] = s;
    }
    __syncthreads();
    if (tid < 64)
        h2[tid] = fmaxf(b2s[tid] + prt[tid] + prt[tid + 64] + prt[tid + 128] + prt[tid + 192], 0.f);
    __syncthreads();

    // ---- fc3: one output per warp (threads 0..127), warp-shuffle reduce ----
    if (tid < 128) {
        int o = tid >> 5, l = tid & 31;
        float s = w3s[o * 64 + l] * h2[l] + w3s[o * 64 + 32 + l] * h2[32 + l];
#pragma unroll
        for (int d = 16; d > 0; d >>= 1) s += __shfl_xor_sync(0xffffffffu, s, d);
        if (l == 0) out[b * 4 + o] = s + b3s[o];
    }
}

// ---------------- host launcher ----------------
extern "C" void kernel_launch(void* const* d_in, const int* in_sizes, int n_in,
                              void* d_out, int out_size)
{
    const float* x  = (const float*)d_in[0];
    const float* kp = (const float*)d_in[1];
    const float* w1 = (const float*)d_in[2];
    const float* b1 = (const float*)d_in[3];
    const float* w2 = (const float*)d_in[4];
    const float* b2 = (const float*)d_in[5];
    const float* w3 = (const float*)d_in[6];
    const float* b3 = (const float*)d_in[7];
    float* out = (float*)d_out;

    cudaFuncSetAttribute(qsim_k1, cudaFuncAttributeMaxDynamicSharedMemorySize, 131072);
    cudaFuncSetAttribute(qsim_k3, cudaFuncAttributeMaxDynamicSharedMemorySize,
                         K3_SMEM_FLOATS * (int)sizeof(float));

    qsim_k1<<<128, NT1, 131072>>>(x, kp);
    qsim_k2<<<128, 512>>>(kp);
    qsim_k3<<<16, 256, K3_SMEM_FLOATS * (int)sizeof(float)>>>(w1, b1, w2, b2, w3, b3, out);
}

// round 17
// speedup vs baseline: 1.0948x; 1.0948x over previous
#include <cuda_runtime.h>
#include <math.h>

#define NT1 1024

typedef unsigned long long u64;

// Scratch (static device arrays — no allocation)
__device__ u64   g_state[32u * 65536u];   // 16 MB: [b][k][b0][b15][idx14], packed (re,im)
__device__ float g_featsP[8 * 16 * 24];   // partial quantum features [part][b][24]

// ---------------- f32x2 packed helpers (sm_103a) ----------------
__device__ __forceinline__ u64 pk2(float x, float y) {
    u64 r; asm("mov.b64 %0, {%1,%2};" : "=l"(r) : "f"(x), "f"(y)); return r;
}
__device__ __forceinline__ u64 f2mul(u64 a, u64 b) {
    u64 d; asm("mul.rn.f32x2 %0, %1, %2;" : "=l"(d) : "l"(a), "l"(b)); return d;
}
__device__ __forceinline__ u64 f2fma(u64 a, u64 b, u64 c) {
    u64 d; asm("fma.rn.f32x2 %0, %1, %2, %3;" : "=l"(d) : "l"(a), "l"(b), "l"(c)); return d;
}
__device__ __forceinline__ u64 f2swap(u64 a) {
    unsigned lo, hi; asm("mov.b64 {%0,%1}, %2;" : "=r"(lo), "=r"(hi) : "l"(a));
    u64 d; asm("mov.b64 %0, {%1,%2};" : "=l"(d) : "r"(hi), "r"(lo)); return d;
}
__device__ __forceinline__ void upk(u64 a, float& x, float& y) {
    asm("mov.b64 {%0,%1}, %2;" : "=f"(x), "=f"(y) : "l"(a));
}

// Bank-conflict-free swizzle; GF(2)-LINEAR: sphys(a^b) = sphys(a)^sphys(b)
// (5*y for 2-bit y = y|(y<<2), carry-free). Used to split base/lane parts.
__device__ __host__ __forceinline__ constexpr int sphys(int idx) {
    return idx ^ ((idx >> 2) & 12) ^ (5 * ((idx >> 6) & 3));
}

// RY on packed pair: u' = c*u - s*v ; v' = s*u + c*v (elementwise on re/im)
template<int T, int N>
__device__ __forceinline__ void ryg(u64* a, u64 cc, u64 ss, u64 nss) {
#pragma unroll
    for (int m = 0; m < N; m++) {
        if (m & (1 << T)) continue;
        int v = m | (1 << T);
        u64 au = a[m], av = a[v];
        a[m] = f2fma(cc, au, f2mul(nss, av));
        a[v] = f2fma(cc, av, f2mul(ss, au));
    }
}
// RX: u' = c*u + (s,-s)*swap(v) ; v' = c*v + (s,-s)*swap(u)
template<int T, int N>
__device__ __forceinline__ void rxg(u64* a, u64 cc, u64 sp) {
#pragma unroll
    for (int m = 0; m < N; m++) {
        if (m & (1 << T)) continue;
        int v = m | (1 << T);
        u64 au = a[m], av = a[v];
        a[m] = f2fma(cc, au, f2mul(sp, f2swap(av)));
        a[v] = f2fma(cc, av, f2mul(sp, f2swap(au)));
    }
}
template<int C, int T, int N>
__device__ __forceinline__ void cng(u64* a) {
#pragma unroll
    for (int m = 0; m < N; m++) {
        if (!(m & (1 << C)) || (m & (1 << T))) continue;
        int v = m | (1 << T);
        u64 t = a[m]; a[m] = a[v]; a[v] = t;
    }
}

// ---------------- compile-time parity masks for the 36-CNOT cascade ----------------
// inner: e5 bits (bit4=wire11 .. bit0=wire15); outer: idx14 bits 13..4 (wires 1..10)
struct Masks { unsigned inner[12]; unsigned outer14[12]; unsigned w0f[12]; };
__host__ __device__ constexpr Masks compute_masks() {
    Masks M{};
    int cs[36] = {}, ts2[36] = {}; int n = 0;
    for (int i = 0; i < 12; i++) {
        cs[n] = i + 1; ts2[n] = i; n++;
        cs[n] = i + 3; ts2[n] = i; n++;
        cs[n] = i + 4; ts2[n] = i; n++;
    }
    for (int w = 0; w < 12; w++) {
        unsigned m = 1u << w;
        for (int j = 35; j >= 0; --j)
            if ((m >> ts2[j]) & 1u) m ^= 1u << cs[j];
        unsigned inner = 0, outer = 0;
        M.w0f[w] = m & 1u;
        for (int ww = 1; ww <= 10; ++ww)
            if ((m >> ww) & 1u) outer |= 1u << (14 - ww);
        for (int ww = 11; ww <= 15; ++ww)
            if ((m >> ww) & 1u) inner |= 1u << (15 - ww);
        M.inner[w] = inner; M.outer14[w] = outer;
    }
    return M;
}

// ---------------- kernel 1: 14-qubit smem-resident simulation ----------------
// 128 blocks: bi = ((b*2 + k)*2 + b0)*2 + b15. Pooling folded into prologue.
// Offsets via linearity of sphys: off[e] = sphys(base) ^ const.
extern "C" __global__ void __launch_bounds__(NT1) qsim_k1(
    const float* __restrict__ x, const float* __restrict__ kp)
{
    extern __shared__ u64 S[];           // 16384 amps (swizzled)
    __shared__ float tws[16][2];
    __shared__ float ptrig[5][2];
    int tid = threadIdx.x;
    int bi = blockIdx.x;
    int b = bi >> 3, k = (bi >> 2) & 1, bb0 = (bi >> 1) & 1, bb15 = bi & 1;

    if (tid < 16) {
        // fused 7x7 avg pool for cell tid of batch b
        int r = tid >> 2, c = tid & 3;
        const float* px = x + b * 784 + r * 7 * 28 + c * 7;
        float s = 0.f;
#pragma unroll
        for (int u = 0; u < 7; u++)
#pragma unroll
            for (int v = 0; v < 7; v++) s += px[u * 28 + v];
        float ang = s * (1.f / 49.f);
        if (tid == 0) ang += kp[k * 5];      // fold iter-0 RY(p0) on wire 0
        float h = 0.5f * ang;
        tws[tid][0] = cosf(h); tws[tid][1] = sinf(h);
    }
    if (tid < 5) {
        float h = 0.5f * kp[k * 5 + tid];
        ptrig[tid][0] = cosf(h); ptrig[tid][1] = sinf(h);
    }
    __syncthreads();

    float c0 = ptrig[0][0], s0 = ptrig[0][1];
    float c1 = ptrig[1][0], s1 = ptrig[1][1];
    float c2 = ptrig[2][0], s2 = ptrig[2][1];
    float c3 = ptrig[3][0], s3 = ptrig[3][1];
    float c4 = ptrig[4][0], s4 = ptrig[4][1];
    u64 cc0 = pk2(c0, c0), ss0 = pk2(s0, s0), ns0 = pk2(-s0, -s0);
    u64 cc1 = pk2(c1, c1), ss1 = pk2(s1, s1), ns1 = pk2(-s1, -s1);
    u64 cc2 = pk2(c2, c2), ss2 = pk2(s2, s2), ns2 = pk2(-s2, -s2);
    u64 cc3 = pk2(c3, c3), sp3 = pk2(s3, -s3);
    u64 cc4 = pk2(c4, c4), sp4 = pk2(s4, -s4);

    int stid = sphys(tid);   // linear part for strided loops (stride bits ^ tid bits disjoint)

    // ---- init: product state, factored (encoder folded; CNOT(0,3) as table swap) ----
    {
        float A = tws[0][bb0] * tws[15][bb15];
        float tc[14], ts[14];
#pragma unroll
        for (int w = 1; w <= 14; ++w) { tc[w - 1] = tws[w][0]; ts[w - 1] = tws[w][1]; }
        if (bb0) { float t = tc[2]; tc[2] = ts[2]; ts[2] = t; }   // X on wire 3 when wire0==1
        // P over j bits 0..9 (tables 13..4), scaled by A
        float P = A;
#pragma unroll
        for (int j = 0; j < 10; j++)
            P *= ((tid >> j) & 1) ? ts[13 - j] : tc[13 - j];
        // two-level factor tables for j bits 10..13 (tables 3..0)
        float fa[4], fb[4];
#pragma unroll
        for (int q = 0; q < 4; q++) {
            fa[q] = ((q & 1) ? ts[3] : tc[3]) * ((q & 2) ? ts[2] : tc[2]);  // j bits 10,11
            fb[q] = ((q & 1) ? ts[1] : tc[1]) * ((q & 2) ? ts[0] : tc[0]);  // j bits 12,13
        }
#pragma unroll
        for (int m = 0; m < 16; m++) {
            float amp = P * fa[m & 3] * fb[m >> 2];
            S[stid ^ sphys(m << 10)] = pk2(amp, 0.f);
        }
    }
    __syncthreads();

    // ---- iteration 0 (wires 1,3,4 local; wire-0 ops folded) ----
    for (int g = tid; g < 2048; g += NT1) {
        // mask bits {13,11,10}; non-mask: bits 0..9 and bit 12
        int base = (g & 0x3FF) | ((g >> 10) << 12);
        int pb = sphys(base);
        int off[8]; u64 a[8];
#pragma unroll
        for (int e = 0; e < 8; e++) {
            off[e] = pb ^ sphys(((e & 3) << 10) | ((e >> 2) << 13));
            a[e] = S[off[e]];
        }
        ryg<1, 8>(a, cc1, ss1, ns1);  // RY(p1) wire 3
        ryg<2, 8>(a, cc2, ss2, ns2);  // RY(p2) wire 1
        cng<2, 0, 8>(a);              // CNOT(1,4)
        cng<1, 2, 8>(a);              // CNOT(3,1)
        rxg<0, 8>(a, cc3, sp3);       // RX(p3) wire 4
        rxg<2, 8>(a, cc4, sp4);       // RX(p4) wire 1
#pragma unroll
        for (int e = 0; e < 8; e++) S[off[e]] = a[e];
    }
    __syncthreads();

    // ---- iterations 1..10 (generic 4-bit group: wires i,i+1,i+3,i+4) ----
    // FULLY UNROLLED: masks/shifts and lane-swizzles are compile-time constants.
#pragma unroll
    for (int i = 1; i <= 10; i++) {
        const int B0 = 10 - i, B2 = 13 - i;
        {
            int g = tid;                 // 1024 groups, 1024 threads
            int low = g & ((1 << B0) - 1);
            int rest = g >> B0;
            int base = low | ((rest & 1) << (B0 + 2)) | ((rest >> 1) << (B0 + 5));
            int pb = sphys(base);
            int off[16]; u64 a[16];
#pragma unroll
            for (int e = 0; e < 16; e++) {
                off[e] = pb ^ sphys(((e & 3) << B0) | ((e >> 2) << B2));
                a[e] = S[off[e]];
            }
            ryg<3, 16>(a, cc0, ss0, ns0);   // RY(p0) wire i
            cng<3, 1, 16>(a);               // CNOT(i, i+3)
            ryg<1, 16>(a, cc1, ss1, ns1);   // RY(p1) wire i+3
            ryg<2, 16>(a, cc2, ss2, ns2);   // RY(p2) wire i+1
            cng<2, 0, 16>(a);               // CNOT(i+1, i+4)
            cng<1, 2, 16>(a);               // CNOT(i+3, i+1)
            rxg<0, 16>(a, cc3, sp3);        // RX(p3) wire i+4
            rxg<2, 16>(a, cc4, sp4);        // RX(p4) wire i+1
#pragma unroll
            for (int e = 0; e < 16; e++) S[off[e]] = a[e];
        }
        __syncthreads();
    }

    // ---- spill sub-state (coalesced); iteration 11 handled in k2 ----
    u64* outp = g_state + (size_t)bi * 16384u;
#pragma unroll
    for (int m = 0; m < 16; m++)
        outp[tid + (m << 10)] = S[stid ^ sphys(m << 10)];
}

// ---------------- kernel 2: iteration 11 + measurement (5-bit WHT) ----------------
// 256 blocks = 32 statevectors x 8 partial slices; 256 threads, 1 group/thread.
// 256-thread launch bounds -> 255-reg cap, no spills for the 32-amp register group.
extern "C" __global__ void __launch_bounds__(256) qsim_k2(const float* __restrict__ kp) {
    constexpr Masks MK = compute_masks();
    int tid = threadIdx.x;
    int blk = blockIdx.x;
    int bk = blk >> 3, part = blk & 7;
    int b = bk >> 1, k = bk & 1;

    float c0, s0, c1, s1, c2, s2, c3, s3, c4, s4;
    { float h = 0.5f * kp[k * 5 + 0]; c0 = cosf(h); s0 = sinf(h); }
    { float h = 0.5f * kp[k * 5 + 1]; c1 = cosf(h); s1 = sinf(h); }
    { float h = 0.5f * kp[k * 5 + 2]; c2 = cosf(h); s2 = sinf(h); }
    { float h = 0.5f * kp[k * 5 + 3]; c3 = cosf(h); s3 = sinf(h); }
    { float h = 0.5f * kp[k * 5 + 4]; c4 = cosf(h); s4 = sinf(h); }
    u64 cc0 = pk2(c0, c0), ss0 = pk2(s0, s0), ns0 = pk2(-s0, -s0);
    u64 cc1 = pk2(c1, c1), ss1 = pk2(s1, s1), ns1 = pk2(-s1, -s1);
    u64 cc2 = pk2(c2, c2), ss2 = pk2(s2, s2), ns2 = pk2(-s2, -s2);
    u64 cc3 = pk2(c3, c3), sp3 = pk2(s3, -s3);
    u64 cc4 = pk2(c4, c4), sp4 = pk2(s4, -s4);

    const u64* base = g_state + (size_t)bk * 65536u;
    float acc[12];
#pragma unroll
    for (int w = 0; w < 12; w++) acc[w] = 0.f;

    // 2048 groups per statevector: gi = b0(bit10) | idx14_hi(10 bits); 1 per thread
    {
        int gi = part * 256 + tid;
        int b0 = gi >> 10, hi = gi & 1023;
        const u64* p = base + b0 * 32768 + hi * 16;
        u64 a[32];
#pragma unroll
        for (int o = 0; o < 16; o++) {       // o bits 3..0 = wires 11,12,13,14
            a[(o << 1)]     = p[o];          // b15 (wire15) = 0
            a[(o << 1) | 1] = p[o + 16384];  // wire15 = 1
        }
        // iteration 11 (full):
        ryg<4, 32>(a, cc0, ss0, ns0);   // RY(p0) wire 11
        cng<4, 1, 32>(a);               // CNOT(11,14)
        ryg<1, 32>(a, cc1, ss1, ns1);   // RY(p1) wire 14
        ryg<3, 32>(a, cc2, ss2, ns2);   // RY(p2) wire 12
        cng<3, 0, 32>(a);               // CNOT(12,15)
        cng<1, 3, 32>(a);               // CNOT(14,12)
        rxg<0, 32>(a, cc3, sp3);        // RX(p3) wire 15
        rxg<3, 32>(a, cc4, sp4);        // RX(p4) wire 12
        float pr[32];
#pragma unroll
        for (int e = 0; e < 32; e++) {
            float xr, xi; upk(a[e], xr, xi);
            pr[e] = xr * xr + xi * xi;
        }
        // 5-bit Walsh-Hadamard: pr[m] <- sum_e (-1)^{popc(m&e)} pr[e]
#pragma unroll
        for (int bit = 1; bit < 32; bit <<= 1) {
#pragma unroll
            for (int m = 0; m < 32; m++) {
                if (m & bit) continue;
                float u = pr[m], v = pr[m | bit];
                pr[m] = u + v; pr[m | bit] = u - v;
            }
        }
        int base14 = hi << 4;
#pragma unroll
        for (int w = 0; w < 12; w++) {
            float s = pr[MK.inner[w]];
            int par = (__popc(base14 & MK.outer14[w]) + (b0 & MK.w0f[w])) & 1;
            acc[w] += par ? -s : s;
        }
    }
    // deterministic reduction (8 warps)
#pragma unroll
    for (int w = 0; w < 12; w++)
        for (int o = 16; o > 0; o >>= 1)
            acc[w] += __shfl_xor_sync(0xffffffffu, acc[w], o);
    __shared__ float part_s[8][12];
    int wid = tid >> 5, lane = tid & 31;
    if (lane == 0) {
#pragma unroll
        for (int w = 0; w < 12; w++) part_s[wid][w] = acc[w];
    }
    __syncthreads();
    if (tid < 12) {
        float s = 0.f;
#pragma unroll
        for (int r = 0; r < 8; r++) s += part_s[r][tid];
        g_featsP[part * 384 + b * 24 + k * 12 + tid] = s;
    }
}

// ---------------- kernel 3: tiny MLP 24->128->64->4 ----------------
// 16 blocks (one per batch item), 256 threads. Weights staged via float4
// global loads; padded smem strides (25 / 129) keep LDS conflict-free.
#define K3_SMEM_FLOATS 12380
extern "C" __global__ void __launch_bounds__(256) qsim_k3(
    const float* __restrict__ w1, const float* __restrict__ bb1,
    const float* __restrict__ w2, const float* __restrict__ bb2,
    const float* __restrict__ w3, const float* __restrict__ bb3,
    float* __restrict__ out)
{
    extern __shared__ float sm[];
    float* w1s = sm;             // 128 x stride 25  (3200)
    float* w2s = sm + 3200;      // 64 x stride 129  (8256)
    float* w3s = sm + 11456;     // 256
    float* b1s = sm + 11712;     // 128
    float* b2s = sm + 11840;     // 64
    float* b3s = sm + 11904;     // 4
    float* fts = sm + 11908;     // 24
    float* h1  = sm + 11936;     // 128
    float* h2  = sm + 12064;     // 64
    float* prt = sm + 12124;     // 256

    int tid = threadIdx.x;
    int b = blockIdx.x;

    // ---- stage weights (float4 global reads, scalar padded STS) ----
    const float4* w1v = (const float4*)w1;
    for (int t = tid; t < 768; t += 256) {
        float4 v = w1v[t];
        int base = 4 * t, row = base / 24, col = base % 24;
        float* d = w1s + row * 25 + col;
        d[0] = v.x; d[1] = v.y; d[2] = v.z; d[3] = v.w;
    }
    const float4* w2v = (const float4*)w2;
    for (int t = tid; t < 2048; t += 256) {
        float4 v = w2v[t];
        int base = 4 * t, row = base >> 7, col = base & 127;
        float* d = w2s + row * 129 + col;
        d[0] = v.x; d[1] = v.y; d[2] = v.z; d[3] = v.w;
    }
    if (tid < 64) {
        float4 v = ((const float4*)w3)[tid];
        float* d = w3s + 4 * tid;
        d[0] = v.x; d[1] = v.y; d[2] = v.z; d[3] = v.w;
    }
    if (tid < 128) b1s[tid] = bb1[tid];
    if (tid < 64)  b2s[tid] = bb2[tid];
    if (tid < 4)   b3s[tid] = bb3[tid];
    if (tid < 24) {
        float s = 0.f;
#pragma unroll
        for (int r = 0; r < 8; r++) s += g_featsP[r * 384 + b * 24 + tid];
        fts[tid] = s;
    }
    __syncthreads();

    // ---- fc1: one output unit per thread (threads 0..127) ----
    if (tid < 128) {
        float s = b1s[tid];
        const float* wr = w1s + tid * 25;
#pragma unroll
        for (int i = 0; i < 24; i++) s += wr[i] * fts[i];
        h1[tid] = fmaxf(s, 0.f);
    }
    __syncthreads();

    // ---- fc2: 64 units, 4 threads per unit (split the 128-dot into 32s) ----
    {
        int j = tid & 63, h = tid >> 6;
        const float* wr = w2s + j * 129 + h * 32;
        const float* hr = h1 + h * 32;
        float s = 0.f;
#pragma unroll
        for (int i = 0; i < 32; i++) s += wr[i] * hr[i];
        prt[tid] = s;
    }
    __syncthreads();
    if (tid < 64)
        h2[tid] = fmaxf(b2s[tid] + prt[tid] + prt[tid + 64] + prt[tid + 128] + prt[tid + 192], 0.f);
    __syncthreads();

    // ---- fc3: one output per warp (threads 0..127), warp-shuffle reduce ----
    if (tid < 128) {
        int o = tid >> 5, l = tid & 31;
        float s = w3s[o * 64 + l] * h2[l] + w3s[o * 64 + 32 + l] * h2[32 + l];
#pragma unroll
        for (int d = 16; d > 0; d >>= 1) s += __shfl_xor_sync(0xffffffffu, s, d);
        if (l == 0) out[b * 4 + o] = s + b3s[o];
    }
}

// ---------------- host launcher ----------------
extern "C" void kernel_launch(void* const* d_in, const int* in_sizes, int n_in,
                              void* d_out, int out_size)
{
    const float* x  = (const float*)d_in[0];
    const float* kp = (const float*)d_in[1];
    const float* w1 = (const float*)d_in[2];
    const float* b1 = (const float*)d_in[3];
    const float* w2 = (const float*)d_in[4];
    const float* b2 = (const float*)d_in[5];
    const float* w3 = (const float*)d_in[6];
    const float* b3 = (const float*)d_in[7];
    float* out = (float*)d_out;

    cudaFuncSetAttribute(qsim_k1, cudaFuncAttributeMaxDynamicSharedMemorySize, 131072);
    cudaFuncSetAttribute(qsim_k3, cudaFuncAttributeMaxDynamicSharedMemorySize,
                         K3_SMEM_FLOATS * (int)sizeof(float));

    qsim_k1<<<128, NT1, 131072>>>(x, kp);
    qsim_k2<<<256, 256>>>(kp);
    qsim_k3<<<16, 256, K3_SMEM_FLOATS * (int)sizeof(float)>>>(w1, b1, w2, b2, w3, b3, out);
}